// round 6
// baseline (speedup 1.0000x reference)
#include <cuda_runtime.h>
#include <math.h>

#define B_  8
#define H_  384
#define W_  512
#define HW_ (H_ * W_)
#define NPIX (B_ * HW_)

#define K0 (-1.0f / 12.0f)
#define K1 (2.0f / 3.0f)
#define K3 (-2.0f / 3.0f)
#define K4 (1.0f / 12.0f)

#define TX 128           // interior tile cols
#define TY 8             // interior tile rows
#define SW 136           // smem row width (2 pad + 2 halo + 128 + 2 halo + 2 pad)
#define SH 12            // smem rows (2 halo + 8 + 2 halo)

// ---- scratch ----
__device__ __align__(16) float  g_flowf[B_ * HW_ * 2];   // interleaved [B][HW][2]
__device__ __align__(16) float  g_flowb[B_ * HW_ * 2];
__device__ double g_acc[3];   // 0 = energy, 1 = entropy-sum, 2 = epe-sum

__device__ __forceinline__ float sigm(float x) { return 1.0f / (1.0f + __expf(-x)); }

__device__ __forceinline__ void ld4a(const float* __restrict__ p, float* a) {
    float4 v = *reinterpret_cast<const float4*>(p);
    a[0] = v.x; a[1] = v.y; a[2] = v.z; a[3] = v.w;
}
__device__ __forceinline__ void st4a(float* p, const float* a) {
    float4 v; v.x = a[0]; v.y = a[1]; v.z = a[2]; v.w = a[3];
    *reinterpret_cast<float4*>(p) = v;
}
__device__ __forceinline__ void zero4(float* d) { d[0]=d[1]=d[2]=d[3]=0.0f; }

struct Bil {
    float w00, w10, w01, w11;
    int o00, o10, o01, o11;
};
__device__ __forceinline__ Bil bilin(float xq, float yq) {
    float x0f = floorf(xq), y0f = floorf(yq);
    float wx = xq - x0f, wy = yq - y0f;
    int x0 = (int)x0f, y0 = (int)y0f;
    int x1 = x0 + 1,   y1 = y0 + 1;
    float vx0 = (x0 >= 0 && x0 <= W_ - 1) ? 1.0f : 0.0f;
    float vx1 = (x1 >= 0 && x1 <= W_ - 1) ? 1.0f : 0.0f;
    float vy0 = (y0 >= 0 && y0 <= H_ - 1) ? 1.0f : 0.0f;
    float vy1 = (y1 >= 0 && y1 <= H_ - 1) ? 1.0f : 0.0f;
    Bil r;
    r.w00 = (1.0f - wx) * (1.0f - wy) * vx0 * vy0;
    r.w10 = wx * (1.0f - wy) * vx1 * vy0;
    r.w01 = (1.0f - wx) * wy * vx0 * vy1;
    r.w11 = wx * wy * vx1 * vy1;
    int xc0 = min(max(x0, 0), W_ - 1), xc1 = min(max(x1, 0), W_ - 1);
    int yc0 = min(max(y0, 0), H_ - 1), yc1 = min(max(y1, 0), H_ - 1);
    r.o00 = yc0 * W_ + xc0; r.o10 = yc0 * W_ + xc1;
    r.o01 = yc1 * W_ + xc0; r.o11 = yc1 * W_ + xc1;
    return r;
}

__device__ __forceinline__ void blockReduceAdd(double* dst, float v) {
    __shared__ float ws[32];
    int lane = threadIdx.x & 31;
    int wid  = threadIdx.x >> 5;
#pragma unroll
    for (int o = 16; o; o >>= 1) v += __shfl_down_sync(0xffffffffu, v, o);
    __syncthreads();
    if (lane == 0) ws[wid] = v;
    __syncthreads();
    if (wid == 0) {
        int nw = (blockDim.x + 31) >> 5;
        v = (lane < nw) ? ws[lane] : 0.0f;
#pragma unroll
        for (int o = 16; o; o >>= 1) v += __shfl_down_sync(0xffffffffu, v, o);
        if (lane == 0) atomicAdd(dst, (double)v);
    }
}

__global__ void zero_acc_kernel() {
    if (threadIdx.x < 3) g_acc[threadIdx.x] = 0.0;
}

// Pass 1: flow samples (interleaved out) + entropy + EPE, 4 px/thread
__global__ void sample_kernel(const float* __restrict__ mf, const float* __restrict__ lvf,
                              const float* __restrict__ nf,
                              const float* __restrict__ mb, const float* __restrict__ lvb,
                              const float* __restrict__ nb,
                              const float* __restrict__ tgt) {
    int t = blockIdx.x * blockDim.x + threadIdx.x;
    int b  = t / (HW_ / 4);
    int r4 = t - b * (HW_ / 4);
    int i0 = b * 2 * HW_ + r4 * 4;
    int i1 = i0 + HW_;
    int oi = (b * HW_ + r4 * 4) * 2;

    float m0[4], m1[4], l0[4], l1[4], n0[4], n1[4], t0[4], t1[4];
    ld4a(mf  + i0, m0); ld4a(mf  + i1, m1);
    ld4a(lvf + i0, l0); ld4a(lvf + i1, l1);
    ld4a(nf  + i0, n0); ld4a(nf  + i1, n1);
    ld4a(tgt + i0, t0); ld4a(tgt + i1, t1);

    float fo[8];
    float ent = 0.0f, epe = 0.0f;
#pragma unroll
    for (int i = 0; i < 4; i++) {
        fo[2 * i]     = m0[i] + __expf(0.5f * l0[i]) * n0[i];
        fo[2 * i + 1] = m1[i] + __expf(0.5f * l1[i]) * n1[i];
        ent += l0[i] + l1[i];
        float d0 = m0[i] - t0[i], d1 = m1[i] - t1[i];
        epe += sqrtf(d0 * d0 + d1 * d1);
    }
    st4a(g_flowf + oi, fo); st4a(g_flowf + oi + 4, fo + 4);

    ld4a(mb  + i0, m0); ld4a(mb  + i1, m1);
    ld4a(lvb + i0, l0); ld4a(lvb + i1, l1);
    ld4a(nb  + i0, n0); ld4a(nb  + i1, n1);
#pragma unroll
    for (int i = 0; i < 4; i++) {
        fo[2 * i]     = m0[i] + __expf(0.5f * l0[i]) * n0[i];
        fo[2 * i + 1] = m1[i] + __expf(0.5f * l1[i]) * n1[i];
        ent += l0[i] + l1[i];
    }
    st4a(g_flowb + oi, fo); st4a(g_flowb + oi + 4, fo + 4);

    blockReduceAdd(&g_acc[1], ent);
    blockReduceAdd(&g_acc[2], epe);
}

// Fused pass: per-direction energy (mask/data/fb/smooth) + 5-tap gradient term.
// Block = 128x8 interior tile, diff stored in smem with +-2 halo.
__global__ void __launch_bounds__(256) fused_dir_kernel(
        const float* __restrict__ img_a,
        const float* __restrict__ img_b, int dirn) {
    __shared__ __align__(16) float sd[3][SH][SW];

    const float* __restrict__ flow_a = dirn ? g_flowb : g_flowf;
    const float* __restrict__ flow_b = dirn ? g_flowf : g_flowb;

    int bx  = blockIdx.x & 3;
    int tmp = blockIdx.x >> 2;
    int ty  = tmp % (H_ / TY);
    int b   = tmp / (H_ / TY);
    int xg  = bx * TX;
    int y0  = ty * TY;
    int tid = threadIdx.x;

    const float* fap = flow_a + (size_t)(b * HW_) * 2;
    const float* fbp = flow_b + (size_t)(b * HW_) * 2;
    const float* ia  = img_a + (size_t)b * 3 * HW_;
    const float* ib  = img_b + (size_t)b * 3 * HW_;

    float e = 0.0f;
    float m_reg[4];

    // ---- Phase A: interior, full energy terms + diff into smem ----
    int rr = tid >> 5;              // 0..7
    int xi = (tid & 31) * 4;        // 0..124
    int y  = y0 + rr;
    int x  = xg + xi;
    int r  = y * W_ + x;
    {
        float f[8];
        ld4a(fap + (size_t)r * 2, f);
        ld4a(fap + (size_t)r * 2 + 4, f + 4);
        bool hasD = (y < H_ - 1);
        float fd[8];
        if (hasD) {
            ld4a(fap + (size_t)(r + W_) * 2, fd);
            ld4a(fap + (size_t)(r + W_) * 2 + 4, fd + 4);
        } else {
            zero4(fd); zero4(fd + 4);
        }
        float fr0 = 0.0f, fr1 = 0.0f;
        bool hasR = (x + 4 < W_);
        if (hasR) {
            float2 t2 = *reinterpret_cast<const float2*>(fap + (size_t)(r + 4) * 2);
            fr0 = t2.x; fr1 = t2.y;
        }
        float a0[4], a1[4], a2[4];
        ld4a(ia + r, a0);
        ld4a(ia + HW_ + r, a1);
        ld4a(ia + 2 * HW_ + r, a2);

#pragma unroll
        for (int j = 0; j < 4; j++) {
            float fa0 = f[2 * j], fa1 = f[2 * j + 1];
            float xq = (float)(x + j) + fa0;
            float yq = (float)y + fa1;

            float mx = sigm(xq + 0.5f) * (1.0f - sigm(xq - ((float)W_ - 0.5f)));
            float my = sigm(yq + 0.5f) * (1.0f - sigm(yq - ((float)H_ - 0.5f)));
            float bmask = mx * my;

            Bil bl = bilin(xq, yq);

            float2 g00 = *reinterpret_cast<const float2*>(fbp + (size_t)bl.o00 * 2);
            float2 g10 = *reinterpret_cast<const float2*>(fbp + (size_t)bl.o10 * 2);
            float2 g01 = *reinterpret_cast<const float2*>(fbp + (size_t)bl.o01 * 2);
            float2 g11 = *reinterpret_cast<const float2*>(fbp + (size_t)bl.o11 * 2);
            float fw0 = bl.w00 * g00.x + bl.w10 * g10.x + bl.w01 * g01.x + bl.w11 * g11.x;
            float fw1 = bl.w00 * g00.y + bl.w10 * g10.y + bl.w01 * g01.y + bl.w11 * g11.y;

            float mag = fa0 * fa0 + fa1 * fa1 + fw0 * fw0 + fw1 * fw1;
            float d0 = fa0 + fw0, d1 = fa1 + fw1;
            float D = d0 * d0 + d1 * d1;
            float occ = 1.0f - sigm(D - (0.01f * mag + 0.5f));
            float m = bmask * occ;
            m_reg[j] = m;

            float A = 0.0f;
            {
                const float* c0 = ib;
                float v = bl.w00 * c0[bl.o00] + bl.w10 * c0[bl.o10]
                        + bl.w01 * c0[bl.o01] + bl.w11 * c0[bl.o11];
                float dd = a0[j] - v;
                sd[0][rr + 2][xi + 4 + j] = dd;  A += dd * dd;
            }
            {
                const float* c1 = ib + HW_;
                float v = bl.w00 * c1[bl.o00] + bl.w10 * c1[bl.o10]
                        + bl.w01 * c1[bl.o01] + bl.w11 * c1[bl.o11];
                float dd = a1[j] - v;
                sd[1][rr + 2][xi + 4 + j] = dd;  A += dd * dd;
            }
            {
                const float* c2 = ib + 2 * HW_;
                float v = bl.w00 * c2[bl.o00] + bl.w10 * c2[bl.o10]
                        + bl.w01 * c2[bl.o01] + bl.w11 * c2[bl.o11];
                float dd = a2[j] - v;
                sd[2][rr + 2][xi + 4 + j] = dd;  A += dd * dd;
            }

            e += (1.0f - m) + sqrtf(A + 1e-5f) * m + sqrtf(D + 1e-5f) * m;

            float s = 0.0f;
            if (x + j < W_ - 1) {
                float nx0 = (j < 3) ? f[2 * j + 2] : fr0;
                float nx1 = (j < 3) ? f[2 * j + 3] : fr1;
                float q0 = nx0 - fa0, q1 = nx1 - fa1;
                s += q0 * q0 + q1 * q1;
            }
            if (hasD) {
                float q0 = fd[2 * j] - fa0, q1 = fd[2 * j + 1] - fa1;
                s += q0 * q0 + q1 * q1;
            }
            e += sqrtf(s + 1e-5f);
        }
    }

    // ---- Phase B: y-halo rows (diff only): 4 rows x 128 cols, 2 px/thread ----
    {
        int hr  = tid >> 6;                       // 0..3
        int hxi = (tid & 63) * 2;                 // 0..126
        int yy   = (hr < 2) ? (y0 - 2 + hr) : (y0 + TY + hr - 2);
        int srow = (hr < 2) ? hr : (TY + hr);     // 0,1,10,11
        int hx = xg + hxi;
        if (yy >= 0 && yy < H_) {
            int r2 = yy * W_ + hx;
            float fh[4];
            ld4a(fap + (size_t)r2 * 2, fh);
#pragma unroll
            for (int j = 0; j < 2; j++) {
                float xq = (float)(hx + j) + fh[2 * j];
                float yq = (float)yy + fh[2 * j + 1];
                Bil bl = bilin(xq, yq);
#pragma unroll
                for (int c = 0; c < 3; c++) {
                    const float* ibc = ib + c * HW_;
                    float v = bl.w00 * ibc[bl.o00] + bl.w10 * ibc[bl.o10]
                            + bl.w01 * ibc[bl.o01] + bl.w11 * ibc[bl.o11];
                    sd[c][srow][4 + hxi + j] = ia[c * HW_ + r2 + j] - v;
                }
            }
        } else {
#pragma unroll
            for (int c = 0; c < 3; c++) {
                sd[c][srow][4 + hxi]     = 0.0f;
                sd[c][srow][4 + hxi + 1] = 0.0f;
            }
        }
    }

    // ---- Phase C: x-halo cols (diff only): 12 rows x 4 px ----
    if (tid < SH * 4) {
        int row = tid >> 2;                        // 0..11
        int k   = tid & 3;                         // 0..3
        int yy  = y0 - 2 + row;
        int hx   = (k < 2) ? (xg - 2 + k) : (xg + TX + k - 2);
        int scol = (k < 2) ? (2 + k) : (4 + TX + k - 2);
        if (yy >= 0 && yy < H_ && hx >= 0 && hx < W_) {
            int r2 = yy * W_ + hx;
            float2 fh = *reinterpret_cast<const float2*>(fap + (size_t)r2 * 2);
            float xq = (float)hx + fh.x;
            float yq = (float)yy + fh.y;
            Bil bl = bilin(xq, yq);
#pragma unroll
            for (int c = 0; c < 3; c++) {
                const float* ibc = ib + c * HW_;
                float v = bl.w00 * ibc[bl.o00] + bl.w10 * ibc[bl.o10]
                        + bl.w01 * ibc[bl.o01] + bl.w11 * ibc[bl.o11];
                sd[c][row][scol] = ia[c * HW_ + r2] - v;
            }
        } else {
#pragma unroll
            for (int c = 0; c < 3; c++) sd[c][row][scol] = 0.0f;
        }
    }

    __syncthreads();

    // ---- Phase D: 5-tap gradient stencil from smem ----
    {
        int sr = rr + 2;
        int sc = xi + 4;
        float Ct[4] = {0.0f, 0.0f, 0.0f, 0.0f};
#pragma unroll
        for (int c = 0; c < 3; c++) {
            float dC[4], dL[4], dR[4], u2[4], u1[4], dn1[4], dn2[4];
            ld4a(&sd[c][sr][sc],     dC);
            ld4a(&sd[c][sr][sc - 4], dL);
            ld4a(&sd[c][sr][sc + 4], dR);
            ld4a(&sd[c][sr - 2][sc], u2);
            ld4a(&sd[c][sr - 1][sc], u1);
            ld4a(&sd[c][sr + 1][sc], dn1);
            ld4a(&sd[c][sr + 2][sc], dn2);

            float gx0 = K0 * dL[2] + K1 * dL[3] + K3 * dC[1] + K4 * dC[2];
            float gx1 = K0 * dL[3] + K1 * dC[0] + K3 * dC[2] + K4 * dC[3];
            float gx2 = K0 * dC[0] + K1 * dC[1] + K3 * dC[3] + K4 * dR[0];
            float gx3 = K0 * dC[1] + K1 * dC[2] + K3 * dR[0] + K4 * dR[1];
            Ct[0] += gx0 * gx0; Ct[1] += gx1 * gx1;
            Ct[2] += gx2 * gx2; Ct[3] += gx3 * gx3;
#pragma unroll
            for (int j = 0; j < 4; j++) {
                float gy = K0 * u2[j] + K1 * u1[j] + K3 * dn1[j] + K4 * dn2[j];
                Ct[j] += gy * gy;
            }
        }
#pragma unroll
        for (int j = 0; j < 4; j++) e += sqrtf(Ct[j] + 1e-5f) * m_reg[j];
    }

    blockReduceAdd(&g_acc[0], e);
}

__global__ void finalize_kernel(float* __restrict__ out) {
    if (threadIdx.x == 0) {
        double energy  = g_acc[0];
        double entropy = 0.5 * g_acc[1];
        out[0] = (float)((energy - entropy) / (double)B_);
        out[1] = (float)(g_acc[2] / (double)NPIX);
    }
}

extern "C" void kernel_launch(void* const* d_in, const int* in_sizes, int n_in,
                              void* d_out, int out_size) {
    const float* meanf   = (const float*)d_in[0];
    const float* logvarf = (const float*)d_in[1];
    const float* meanb   = (const float*)d_in[2];
    const float* logvarb = (const float*)d_in[3];
    const float* img1    = (const float*)d_in[4];
    const float* img2    = (const float*)d_in[5];
    const float* target  = (const float*)d_in[6];
    const float* noisef  = (const float*)d_in[7];
    const float* noiseb  = (const float*)d_in[8];
    float* out = (float*)d_out;

    const int fused_blocks = (W_ / TX) * (H_ / TY) * B_;   // 4*48*8 = 1536

    zero_acc_kernel<<<1, 32>>>();
    sample_kernel<<<NPIX / 4 / 256, 256>>>(meanf, logvarf, noisef,
                                           meanb, logvarb, noiseb, target);
    fused_dir_kernel<<<fused_blocks, 256>>>(img1, img2, 0);
    fused_dir_kernel<<<fused_blocks, 256>>>(img2, img1, 1);
    finalize_kernel<<<1, 32>>>(out);
}

// round 7
// speedup vs baseline: 1.7361x; 1.7361x over previous
#include <cuda_runtime.h>
#include <cuda_fp16.h>
#include <math.h>

#define B_  8
#define H_  384
#define W_  512
#define HW_ (H_ * W_)
#define NPIX (B_ * HW_)

#define K0 (-1.0f / 12.0f)
#define K1 (2.0f / 3.0f)
#define K3 (-2.0f / 3.0f)
#define K4 (1.0f / 12.0f)

// ---- scratch ----
__device__ __align__(16) float  g_flowf[B_ * HW_ * 2];    // interleaved [B][HW][2]
__device__ __align__(16) float  g_flowb[B_ * HW_ * 2];
__device__ __align__(16) __half g_diffh[2 * B_ * 3 * HW_]; // per-direction fp16 diff
__device__ __align__(16) float  g_mask [2 * NPIX];         // per-direction mask
__device__ double g_acc[3];   // 0 = energy, 1 = entropy-sum, 2 = epe-sum

__device__ __forceinline__ float sigm(float x) { return 1.0f / (1.0f + __expf(-x)); }

__device__ __forceinline__ void ld4a(const float* __restrict__ p, float* a) {
    float4 v = *reinterpret_cast<const float4*>(p);
    a[0] = v.x; a[1] = v.y; a[2] = v.z; a[3] = v.w;
}
__device__ __forceinline__ void st4a(float* p, const float* a) {
    float4 v; v.x = a[0]; v.y = a[1]; v.z = a[2]; v.w = a[3];
    *reinterpret_cast<float4*>(p) = v;
}
// load 4 consecutive halves (8B aligned) -> 4 floats
__device__ __forceinline__ void ld4h(const __half* __restrict__ p, float* a) {
    uint2 u = *reinterpret_cast<const uint2*>(p);
    __half2 h01 = *reinterpret_cast<const __half2*>(&u.x);
    __half2 h23 = *reinterpret_cast<const __half2*>(&u.y);
    float2 f01 = __half22float2(h01);
    float2 f23 = __half22float2(h23);
    a[0] = f01.x; a[1] = f01.y; a[2] = f23.x; a[3] = f23.y;
}
__device__ __forceinline__ void zero4(float* d) { d[0]=d[1]=d[2]=d[3]=0.0f; }

__device__ __forceinline__ void blockReduceAdd(double* dst, float v) {
    __shared__ float ws[32];
    int lane = threadIdx.x & 31;
    int wid  = threadIdx.x >> 5;
#pragma unroll
    for (int o = 16; o; o >>= 1) v += __shfl_down_sync(0xffffffffu, v, o);
    __syncthreads();
    if (lane == 0) ws[wid] = v;
    __syncthreads();
    if (wid == 0) {
        int nw = (blockDim.x + 31) >> 5;
        v = (lane < nw) ? ws[lane] : 0.0f;
#pragma unroll
        for (int o = 16; o; o >>= 1) v += __shfl_down_sync(0xffffffffu, v, o);
        if (lane == 0) atomicAdd(dst, (double)v);
    }
}

__global__ void zero_acc_kernel() {
    if (threadIdx.x < 3) g_acc[threadIdx.x] = 0.0;
}

// Pass 1: flow samples (interleaved out) + entropy + EPE, 4 px/thread
__global__ void sample_kernel(const float* __restrict__ mf, const float* __restrict__ lvf,
                              const float* __restrict__ nf,
                              const float* __restrict__ mb, const float* __restrict__ lvb,
                              const float* __restrict__ nb,
                              const float* __restrict__ tgt) {
    int t = blockIdx.x * blockDim.x + threadIdx.x;
    int b  = t / (HW_ / 4);
    int r4 = t - b * (HW_ / 4);
    int i0 = b * 2 * HW_ + r4 * 4;
    int i1 = i0 + HW_;
    int oi = (b * HW_ + r4 * 4) * 2;

    float m0[4], m1[4], l0[4], l1[4], n0[4], n1[4], t0[4], t1[4];
    ld4a(mf  + i0, m0); ld4a(mf  + i1, m1);
    ld4a(lvf + i0, l0); ld4a(lvf + i1, l1);
    ld4a(nf  + i0, n0); ld4a(nf  + i1, n1);
    ld4a(tgt + i0, t0); ld4a(tgt + i1, t1);

    float fo[8];
    float ent = 0.0f, epe = 0.0f;
#pragma unroll
    for (int i = 0; i < 4; i++) {
        fo[2 * i]     = m0[i] + __expf(0.5f * l0[i]) * n0[i];
        fo[2 * i + 1] = m1[i] + __expf(0.5f * l1[i]) * n1[i];
        ent += l0[i] + l1[i];
        float d0 = m0[i] - t0[i], d1 = m1[i] - t1[i];
        epe += sqrtf(d0 * d0 + d1 * d1);
    }
    st4a(g_flowf + oi, fo); st4a(g_flowf + oi + 4, fo + 4);

    ld4a(mb  + i0, m0); ld4a(mb  + i1, m1);
    ld4a(lvb + i0, l0); ld4a(lvb + i1, l1);
    ld4a(nb  + i0, n0); ld4a(nb  + i1, n1);
#pragma unroll
    for (int i = 0; i < 4; i++) {
        fo[2 * i]     = m0[i] + __expf(0.5f * l0[i]) * n0[i];
        fo[2 * i + 1] = m1[i] + __expf(0.5f * l1[i]) * n1[i];
        ent += l0[i] + l1[i];
    }
    st4a(g_flowb + oi, fo); st4a(g_flowb + oi + 4, fo + 4);

    blockReduceAdd(&g_acc[1], ent);
    blockReduceAdd(&g_acc[2], epe);
}

// Pass 2: BOTH directions (blockIdx.y). 1 px/thread. Stores mask + fp16 diff.
__global__ void dir_kernel(const float* __restrict__ img1,
                           const float* __restrict__ img2) {
    int dirn = blockIdx.y;
    const float* __restrict__ flow_a = dirn ? g_flowb : g_flowf;
    const float* __restrict__ flow_b = dirn ? g_flowf : g_flowb;
    const float* __restrict__ img_a  = dirn ? img2 : img1;
    const float* __restrict__ img_b  = dirn ? img1 : img2;

    int p = blockIdx.x * blockDim.x + threadIdx.x;
    int b = p / HW_;
    int r = p - b * HW_;
    int y = r / W_;
    int x = r - y * W_;

    const float* fap = flow_a + (size_t)(b * HW_) * 2;
    float2 fav = *reinterpret_cast<const float2*>(fap + (size_t)r * 2);
    float fa0 = fav.x, fa1 = fav.y;
    float xq = (float)x + fa0;
    float yq = (float)y + fa1;

    // border mask
    float mx = sigm(xq + 0.5f) * (1.0f - sigm(xq - ((float)W_ - 0.5f)));
    float my = sigm(yq + 0.5f) * (1.0f - sigm(yq - ((float)H_ - 0.5f)));
    float bmask = mx * my;

    // bilinear taps
    float x0f = floorf(xq), y0f = floorf(yq);
    float wx = xq - x0f, wy = yq - y0f;
    int x0 = (int)x0f, y0 = (int)y0f;
    int x1 = x0 + 1,   y1 = y0 + 1;
    float vx0 = (x0 >= 0 && x0 <= W_ - 1) ? 1.0f : 0.0f;
    float vx1 = (x1 >= 0 && x1 <= W_ - 1) ? 1.0f : 0.0f;
    float vy0 = (y0 >= 0 && y0 <= H_ - 1) ? 1.0f : 0.0f;
    float vy1 = (y1 >= 0 && y1 <= H_ - 1) ? 1.0f : 0.0f;
    float w00 = (1.0f - wx) * (1.0f - wy) * vx0 * vy0;
    float w10 = wx * (1.0f - wy) * vx1 * vy0;
    float w01 = (1.0f - wx) * wy * vx0 * vy1;
    float w11 = wx * wy * vx1 * vy1;
    int xc0 = min(max(x0, 0), W_ - 1), xc1 = min(max(x1, 0), W_ - 1);
    int yc0 = min(max(y0, 0), H_ - 1), yc1 = min(max(y1, 0), H_ - 1);
    int o00 = yc0 * W_ + xc0, o10 = yc0 * W_ + xc1;
    int o01 = yc1 * W_ + xc0, o11 = yc1 * W_ + xc1;

    // warp flow_b: 4 x 64-bit gathers
    const float* fbp = flow_b + (size_t)(b * HW_) * 2;
    float2 g00 = *reinterpret_cast<const float2*>(fbp + (size_t)o00 * 2);
    float2 g10 = *reinterpret_cast<const float2*>(fbp + (size_t)o10 * 2);
    float2 g01 = *reinterpret_cast<const float2*>(fbp + (size_t)o01 * 2);
    float2 g11 = *reinterpret_cast<const float2*>(fbp + (size_t)o11 * 2);
    float fw0 = w00 * g00.x + w10 * g10.x + w01 * g01.x + w11 * g11.x;
    float fw1 = w00 * g00.y + w10 * g10.y + w01 * g01.y + w11 * g11.y;

    float mag = fa0 * fa0 + fa1 * fa1 + fw0 * fw0 + fw1 * fw1;
    float d0 = fa0 + fw0, d1 = fa1 + fw1;
    float D = d0 * d0 + d1 * d1;
    float occ = 1.0f - sigm(D - (0.01f * mag + 0.5f));
    float m = bmask * occ;
    g_mask[(size_t)dirn * NPIX + p] = m;

    // warp img_b (3 planar channels); store fp16 diff + data term
    const float* ib = img_b + (size_t)b * 3 * HW_;
    const float* ia = img_a + (size_t)b * 3 * HW_;
    __half* dw = g_diffh + ((size_t)dirn * B_ + b) * 3 * HW_ + r;
    float A = 0.0f;
#pragma unroll
    for (int c = 0; c < 3; c++) {
        const float* ibc = ib + c * HW_;
        float v = w00 * ibc[o00] + w10 * ibc[o10] + w01 * ibc[o01] + w11 * ibc[o11];
        float dd = ia[c * HW_ + r] - v;
        dw[c * HW_] = __float2half(dd);
        A += dd * dd;
    }

    float e = (1.0f - m)
            + sqrtf(A + 1e-5f) * m
            + sqrtf(D + 1e-5f) * m;

    // smoothness (float2 neighbor loads)
    float s = 0.0f;
    if (x < W_ - 1) {
        float2 nx = *reinterpret_cast<const float2*>(fap + (size_t)(r + 1) * 2);
        float a0 = nx.x - fa0, a1 = nx.y - fa1;
        s += a0 * a0 + a1 * a1;
    }
    if (y < H_ - 1) {
        float2 nd = *reinterpret_cast<const float2*>(fap + (size_t)(r + W_) * 2);
        float a0 = nd.x - fa0, a1 = nd.y - fa1;
        s += a0 * a0 + a1 * a1;
    }
    e += sqrtf(s + 1e-5f);

    blockReduceAdd(&g_acc[0], e);
}

// Pass 3: BOTH directions (blockIdx.y). 5-tap gradient-constancy on fp16 diff.
// 256-thread blocks, 2 rows per block, 4 px/thread.
__global__ void grad_kernel() {
    int dirn = blockIdx.y;
    int sub = threadIdx.x >> 7;                 // 0 or 1
    int row = blockIdx.x * 2 + sub;             // b*H + y
    int b = row / H_;
    int y = row - b * H_;
    int x = (threadIdx.x & 127) * 4;
    int rbase = y * W_ + x;

    const __half* dp = g_diffh + ((size_t)dirn * B_ + b) * 3 * HW_;
    float m[4];
    ld4a(g_mask + (size_t)dirn * NPIX + (size_t)b * HW_ + rbase, m);

    bool hasL  = (x >= 4);
    bool hasR  = (x + 4 < W_);
    bool hasU2 = (y >= 2), hasU1 = (y >= 1);
    bool hasD1 = (y + 1 < H_), hasD2 = (y + 2 < H_);

    float Ct[4] = {0.0f, 0.0f, 0.0f, 0.0f};
#pragma unroll
    for (int c = 0; c < 3; c++) {
        const __half* Dc = dp + c * HW_;
        int o = rbase;
        float dC[4], dL[4], dR[4], u2[4], u1[4], dn1[4], dn2[4];
        ld4h(Dc + o, dC);
        if (hasL)  ld4h(Dc + o - 4, dL);        else zero4(dL);
        if (hasR)  ld4h(Dc + o + 4, dR);        else zero4(dR);
        if (hasU2) ld4h(Dc + o - 2 * W_, u2);   else zero4(u2);
        if (hasU1) ld4h(Dc + o - W_,     u1);   else zero4(u1);
        if (hasD1) ld4h(Dc + o + W_,     dn1);  else zero4(dn1);
        if (hasD2) ld4h(Dc + o + 2 * W_, dn2);  else zero4(dn2);

        float gx0 = K0 * dL[2] + K1 * dL[3] + K3 * dC[1] + K4 * dC[2];
        float gx1 = K0 * dL[3] + K1 * dC[0] + K3 * dC[2] + K4 * dC[3];
        float gx2 = K0 * dC[0] + K1 * dC[1] + K3 * dC[3] + K4 * dR[0];
        float gx3 = K0 * dC[1] + K1 * dC[2] + K3 * dR[0] + K4 * dR[1];
        Ct[0] += gx0 * gx0; Ct[1] += gx1 * gx1;
        Ct[2] += gx2 * gx2; Ct[3] += gx3 * gx3;

#pragma unroll
        for (int i = 0; i < 4; i++) {
            float gy = K0 * u2[i] + K1 * u1[i] + K3 * dn1[i] + K4 * dn2[i];
            Ct[i] += gy * gy;
        }
    }

    float e = 0.0f;
#pragma unroll
    for (int i = 0; i < 4; i++) e += sqrtf(Ct[i] + 1e-5f) * m[i];

    blockReduceAdd(&g_acc[0], e);
}

__global__ void finalize_kernel(float* __restrict__ out) {
    if (threadIdx.x == 0) {
        double energy  = g_acc[0];
        double entropy = 0.5 * g_acc[1];
        out[0] = (float)((energy - entropy) / (double)B_);
        out[1] = (float)(g_acc[2] / (double)NPIX);
    }
}

extern "C" void kernel_launch(void* const* d_in, const int* in_sizes, int n_in,
                              void* d_out, int out_size) {
    const float* meanf   = (const float*)d_in[0];
    const float* logvarf = (const float*)d_in[1];
    const float* meanb   = (const float*)d_in[2];
    const float* logvarb = (const float*)d_in[3];
    const float* img1    = (const float*)d_in[4];
    const float* img2    = (const float*)d_in[5];
    const float* target  = (const float*)d_in[6];
    const float* noisef  = (const float*)d_in[7];
    const float* noiseb  = (const float*)d_in[8];
    float* out = (float*)d_out;

    zero_acc_kernel<<<1, 32>>>();
    sample_kernel<<<NPIX / 4 / 256, 256>>>(meanf, logvarf, noisef,
                                           meanb, logvarb, noiseb, target);
    {
        dim3 g(NPIX / 256, 2);
        dir_kernel<<<g, 256>>>(img1, img2);
    }
    {
        dim3 g(B_ * H_ / 2, 2);
        grad_kernel<<<g, 256>>>();
    }
    finalize_kernel<<<1, 32>>>(out);
}